// round 16
// baseline (speedup 1.0000x reference)
#include <cuda_runtime.h>
#include <math.h>
#include <stdint.h>

#define NN    50000
#define NE    1000000
#define NG    256
#define ORIG  92
#define ATOMD 64
#define NBR   41
#define FCO   128
#define EPS   1e-5f

// ---------------- scratch (static device globals; no allocation) -------------
__device__ float  g_af[NN * ATOMD];          // atom_fea
__device__ float  g_A1[NN * FCO];            // atom_fea @ fc_W[0:64]
__device__ float  g_A2[NN * FCO];            // atom_fea @ fc_W[64:128]
__device__ float  g_h[(size_t)NE * FCO];     // pre-BN edge hidden, CSR row order
__device__ float  g_summed[NN * ATOMD];      // segment_sum(msg, src)
__device__ float  g_hnode[NN * ATOMD];       // silu(atom_out)
__device__ float  g_logits[NN];
__device__ double g_s1[FCO], g_q1[FCO];      // bn1 sum / sumsq
__device__ double g_s2[ATOMD], g_q2[ATOMD];  // bn2 sum / sumsq
__device__ float  g_bn1_scale[FCO], g_bn1_shift[FCO];
__device__ float  g_bn2_scale[ATOMD], g_bn2_shift[ATOMD];
// CSR by src (rebuilt every launch)
__device__ int    g_cursor[NN];              // counts, then running cursors
__device__ int    g_csr_ptr[NN + 1];
__device__ int    g_pos[NE];                 // edge e -> CSR slot

// ---------------- K0: zero cursors + stats ------------------------------------
__global__ void k_init() {
    int stride = gridDim.x * blockDim.x;
    for (int i = blockIdx.x * blockDim.x + threadIdx.x; i < NN; i += stride)
        g_cursor[i] = 0;
    int t = blockIdx.x * blockDim.x + threadIdx.x;
    if (t < FCO)   { g_s1[t] = 0.0; g_q1[t] = 0.0; }
    if (t < ATOMD) { g_s2[t] = 0.0; g_q2[t] = 0.0; }
}

// ---------------- CSR build: histogram -> scan -> scatter(pos) ----------------
__global__ void k_hist(const int* __restrict__ eidx) {
    int stride = gridDim.x * blockDim.x;
    for (int e = blockIdx.x * blockDim.x + threadIdx.x; e < NE; e += stride)
        atomicAdd(&g_cursor[eidx[e]], 1);
}

__global__ void k_scan() {   // single block, 1024 threads
    __shared__ int ssum[1024];
    int t = threadIdx.x;
    const int CH = (NN + 1023) / 1024;   // 49
    int i0 = t * CH, i1 = i0 + CH; if (i1 > NN) i1 = NN;
    int s = 0;
    for (int i = i0; i < i1; i++) s += g_cursor[i];
    ssum[t] = s;
    __syncthreads();
    for (int off = 1; off < 1024; off <<= 1) {
        int v = (t >= off) ? ssum[t - off] : 0;
        __syncthreads();
        ssum[t] += v;
        __syncthreads();
    }
    int run = ssum[t] - s;   // exclusive base for this thread's range
    for (int i = i0; i < i1; i++) {
        int c = g_cursor[i];
        g_csr_ptr[i] = run;
        g_cursor[i]  = run;
        run += c;
    }
    if (t == 1023) g_csr_ptr[NN] = run;   // == NE
}

__global__ void k_scatter(const int* __restrict__ eidx) {
    int stride = gridDim.x * blockDim.x;
    for (int e = blockIdx.x * blockDim.x + threadIdx.x; e < NE; e += stride)
        g_pos[e] = atomicAdd(&g_cursor[eidx[e]], 1);
}

// ---------------- K1a: atom_fea = x @ emb_W + emb_b + lower_f ----------------
#define NPB 16
__global__ void k_embed(const float* __restrict__ x,
                        const float* __restrict__ lower_f,
                        const float* __restrict__ embW,
                        const float* __restrict__ embB) {
    __shared__ __align__(16) float embW_s[ORIG * ATOMD];   // 23552 B
    __shared__ __align__(16) float x_s[NPB * ORIG];        // 5888 B
    int tid = threadIdx.x;  // 256
    int n0  = blockIdx.x * NPB;
    for (int i = tid; i < ORIG * ATOMD; i += 256) embW_s[i] = embW[i];
    for (int i = tid; i < NPB * ORIG; i += 256) {
        int node = n0 + i / ORIG;
        x_s[i] = (node < NN) ? x[node * ORIG + (i % ORIG)] : 0.f;
    }
    __syncthreads();
    for (int t = tid; t < NPB * ATOMD; t += 256) {
        int i = t >> 6, c = t & 63, node = n0 + i;
        if (node >= NN) continue;
        float acc = 0.f;
        const float4* x4 = (const float4*)(x_s + i * ORIG);
#pragma unroll
        for (int k4 = 0; k4 < ORIG / 4; k4++) {
            float4 xv = x4[k4];
            int k = k4 * 4;
            acc += xv.x * embW_s[(k + 0) * ATOMD + c];
            acc += xv.y * embW_s[(k + 1) * ATOMD + c];
            acc += xv.z * embW_s[(k + 2) * ATOMD + c];
            acc += xv.w * embW_s[(k + 3) * ATOMD + c];
        }
        g_af[node * ATOMD + c] = acc + embB[c] + lower_f[node * ATOMD + c];
    }
}

// ---------------- K1b: A1/A2 = atom_fea @ Wa/Wb (register-tiled) -------------
__global__ void k_proj(const float* __restrict__ fcW) {
    __shared__ __align__(16) float W_s[ATOMD * FCO];   // 32 KB
    __shared__ __align__(16) float at_s[NPB * ATOMD];  // 4 KB
    int tid   = threadIdx.x;        // 256
    int which = blockIdx.y;         // 0 -> A1 (rows 0..63), 1 -> A2 (rows 64..127)
    int n0    = blockIdx.x * NPB;
    const float* Wsrc = fcW + which * ATOMD * FCO;
    for (int i = tid; i < ATOMD * FCO; i += 256) W_s[i] = Wsrc[i];
    for (int i = tid; i < NPB * ATOMD; i += 256) {
        int node = n0 + (i >> 6);
        at_s[i] = (node < NN) ? g_af[node * ATOMD + (i & 63)] : 0.f;
    }
    __syncthreads();
    int j = tid & 127, ig = tid >> 7;   // 2 node-groups of 8
    float acc[8];
#pragma unroll
    for (int r = 0; r < 8; r++) acc[r] = 0.f;
    for (int c = 0; c < ATOMD; c++) {
        float w = W_s[c * FCO + j];
#pragma unroll
        for (int r = 0; r < 8; r++)
            acc[r] += at_s[(ig + 2 * r) * ATOMD + c] * w;
    }
    float* dst = which ? g_A2 : g_A1;
#pragma unroll
    for (int r = 0; r < 8; r++) {
        int node = n0 + ig + 2 * r;
        if (node < NN) dst[node * FCO + j] = acc[r];
    }
}

// ---------------- K2: edge pass 1 — h = A1[src]+A2[dst]+attr@W3+b, stats -----
// Proven R14 body (ECH=8, DEPTH=4, 2 f32x2 chains, 4-edge gather sub-batches).
// New: stores row e at CSR slot g_pos[e] so pass 2 streams sequentially.
#define EPB 512
#define ECH 8
#define DEPTH 4
__global__ void __launch_bounds__(128) k_edge1(
                        const float* __restrict__ eattr,
                        const int* __restrict__ eidx,
                        const float* __restrict__ fcW,
                        const float* __restrict__ fcB) {
    __shared__ __align__(16) float attr_s[DEPTH][ECH][44];  // 5632 B, col41 zeroed
    __shared__ int idx_s[DEPTH][3][ECH];                    // src,dst,pos per buffer
    int tid = threadIdx.x;  // 128 -> output column c

    // packed weight k-pairs: w2[j] = (W[2j,c], W[2j+1,c]); pair 20 = (W[40,c], 0)
    unsigned long long w2[21];
#pragma unroll
    for (int j = 0; j < 20; j++) {
        float wa = fcW[(FCO + 2 * j) * FCO + tid];
        float wb = fcW[(FCO + 2 * j + 1) * FCO + tid];
        asm("mov.b64 %0, {%1,%2};" : "=l"(w2[j]) : "f"(wa), "f"(wb));
    }
    {
        float wa = fcW[(FCO + 40) * FCO + tid];
        asm("mov.b64 %0, {%1,%2};" : "=l"(w2[20]) : "f"(wa), "f"(0.0f));
    }
    float b = fcB[tid];
    float s0 = 0.f, s1 = 0.f, q0 = 0.f, q1 = 0.f;

    // zero padding column 41 in all DEPTH*ECH rows (read as hi lane of pair 20)
    if (tid < DEPTH * ECH) attr_s[tid >> 3][tid & 7][41] = 0.f;

    int e0 = blockIdx.x * EPB;

    // async-stage chunk [ce0, ce0+8) into ring buffer; ALWAYS commits a group
    auto stage = [&](int ce0) {
        if (ce0 < NE) {
            int buf = (ce0 >> 3) & (DEPTH - 1);
            const float* gbase = eattr + (size_t)ce0 * NBR;
            for (int t = tid; t < ECH * NBR; t += 128) {
                int i = t / NBR, k = t - i * NBR;
                uint32_t sa = (uint32_t)__cvta_generic_to_shared(&attr_s[buf][i][k]);
                asm volatile("cp.async.ca.shared.global [%0], [%1], 4;"
                             :: "r"(sa), "l"(gbase + t));
            }
            if (tid < ECH) {
                uint32_t sa = (uint32_t)__cvta_generic_to_shared(&idx_s[buf][0][tid]);
                asm volatile("cp.async.ca.shared.global [%0], [%1], 4;"
                             :: "r"(sa), "l"(eidx + ce0 + tid));
            } else if (tid < 2 * ECH) {
                uint32_t sa = (uint32_t)__cvta_generic_to_shared(&idx_s[buf][1][tid - ECH]);
                asm volatile("cp.async.ca.shared.global [%0], [%1], 4;"
                             :: "r"(sa), "l"(eidx + NE + ce0 + tid - ECH));
            } else if (tid < 3 * ECH) {
                uint32_t sa = (uint32_t)__cvta_generic_to_shared(&idx_s[buf][2][tid - 2 * ECH]);
                asm volatile("cp.async.ca.shared.global [%0], [%1], 4;"
                             :: "r"(sa), "l"(g_pos + ce0 + tid - 2 * ECH));
            }
        }
        asm volatile("cp.async.commit_group;" ::: "memory");
    };

    // prologue: stage chunks 0..2 (3 committed groups)
    stage(e0);
    stage(e0 + ECH);
    stage(e0 + 2 * ECH);

    const int nch = EPB / ECH;   // 64
    for (int ch = 0; ch < nch; ch++) {
        stage(e0 + (ch + 3) * ECH);
        asm volatile("cp.async.wait_group 3;" ::: "memory");  // chunk ch arrived
        __syncthreads();

        int cb = e0 + ch * ECH;
        if (cb < NE) {                      // chunks full-or-empty (NE%8==0)
            int buf = ch & (DEPTH - 1);
#pragma unroll
            for (int g = 0; g < 2; g++) {
                float base[4];
#pragma unroll
                for (int u = 0; u < 4; u++) {
                    int i = g * 4 + u;
                    base[u] = b + g_A1[idx_s[buf][0][i] * FCO + tid]
                                + g_A2[idx_s[buf][1][i] * FCO + tid];
                }
#pragma unroll
                for (int u = 0; u < 4; u++) {
                    int i = g * 4 + u;
                    unsigned long long acc0, acc1;
                    asm("mov.b64 %0, {%1,%2};" : "=l"(acc0) : "f"(base[u]), "f"(0.0f));
                    asm("mov.b64 %0, {%1,%1};" : "=l"(acc1) : "f"(0.0f));
                    const ulonglong2* a16 = (const ulonglong2*)attr_s[buf][i];
#pragma unroll
                    for (int j = 0; j < 10; j++) {
                        ulonglong2 uu = a16[j];
                        asm("fma.rn.f32x2 %0, %1, %2, %0;" : "+l"(acc0) : "l"(uu.x), "l"(w2[2 * j]));
                        asm("fma.rn.f32x2 %0, %1, %2, %0;" : "+l"(acc1) : "l"(uu.y), "l"(w2[2 * j + 1]));
                    }
                    {
                        unsigned long long u20 = ((const unsigned long long*)attr_s[buf][i])[20];
                        asm("fma.rn.f32x2 %0, %1, %2, %0;" : "+l"(acc0) : "l"(u20), "l"(w2[20]));
                    }
                    asm("add.rn.f32x2 %0, %0, %1;" : "+l"(acc0) : "l"(acc1));
                    float lo, hi;
                    asm("mov.b64 {%0,%1}, %2;" : "=f"(lo), "=f"(hi) : "l"(acc0));
                    float h = lo + hi;
                    g_h[(size_t)idx_s[buf][2][i] * FCO + tid] = h;   // CSR slot
                    if (u & 1) { s1 += h; q1 = fmaf(h, h, q1); }
                    else       { s0 += h; q0 = fmaf(h, h, q0); }
                }
            }
        }
        __syncthreads();
    }
    atomicAdd(&g_s1[tid], (double)(s0 + s1));
    atomicAdd(&g_q1[tid], (double)(q0 + q1));
}

// ---------------- K3: finalize bn1 scale/shift --------------------------------
__global__ void k_bn1fin(const float* __restrict__ g1, const float* __restrict__ b1) {
    int c = threadIdx.x;
    double mean = g_s1[c] / (double)NE;
    double var  = g_q1[c] / (double)NE - mean * mean;
    float sc = g1[c] * (float)(1.0 / sqrt(var + (double)EPS));
    g_bn1_scale[c] = sc;
    g_bn1_shift[c] = b1[c] - (float)mean * sc;
}

__device__ __forceinline__ float sigm(float x)  { return __fdividef(1.f, 1.f + __expf(-x)); }
__device__ __forceinline__ float softp(float x) { return fmaxf(x, 0.f) + __logf(1.f + __expf(-fabsf(x))); }

// ---------------- K4: edge pass 2 (CSR-ordered h) — pure streaming -----------
// One warp per node; lane l owns msg columns 2l, 2l+1. Rows [lo,hi) of g_h
// are this node's messages, stored contiguously. Unroll x2 for MLP.
__global__ void __launch_bounds__(256) k_edge2csr() {
    int warp = (blockIdx.x * blockDim.x + threadIdx.x) >> 5;
    int lane = threadIdx.x & 31;
    if (warp >= NN) return;
    int lo = g_csr_ptr[warp], hi = g_csr_ptr[warp + 1];
    int c0 = lane * 2;
    float2 sc_f = *(const float2*)&g_bn1_scale[c0];
    float2 sh_f = *(const float2*)&g_bn1_shift[c0];
    float2 sc_g = *(const float2*)&g_bn1_scale[64 + c0];
    float2 sh_g = *(const float2*)&g_bn1_shift[64 + c0];
    float a0 = 0.f, a1 = 0.f, b0 = 0.f, b1 = 0.f;
    const float* hp = g_h + (size_t)lo * FCO;
    int idx = lo;
    for (; idx + 2 <= hi; idx += 2, hp += 2 * FCO) {
        float2 hf0 = __ldcs((const float2*)(hp + c0));
        float2 hg0 = __ldcs((const float2*)(hp + 64 + c0));
        float2 hf1 = __ldcs((const float2*)(hp + FCO + c0));
        float2 hg1 = __ldcs((const float2*)(hp + FCO + 64 + c0));
        a0 += sigm(sc_f.x * hf0.x + sh_f.x) * softp(sc_g.x * hg0.x + sh_g.x);
        a1 += sigm(sc_f.y * hf0.y + sh_f.y) * softp(sc_g.y * hg0.y + sh_g.y);
        b0 += sigm(sc_f.x * hf1.x + sh_f.x) * softp(sc_g.x * hg1.x + sh_g.x);
        b1 += sigm(sc_f.y * hf1.y + sh_f.y) * softp(sc_g.y * hg1.y + sh_g.y);
    }
    if (idx < hi) {
        float2 hf0 = __ldcs((const float2*)(hp + c0));
        float2 hg0 = __ldcs((const float2*)(hp + 64 + c0));
        a0 += sigm(sc_f.x * hf0.x + sh_f.x) * softp(sc_g.x * hg0.x + sh_g.x);
        a1 += sigm(sc_f.y * hf0.y + sh_f.y) * softp(sc_g.y * hg0.y + sh_g.y);
    }
    *(float2*)&g_summed[(size_t)warp * ATOMD + c0] = make_float2(a0 + b0, a1 + b1);
}

// ---------------- K5: bn2 stats over summed -----------------------------------
__global__ void k_bn2stats() {
    int c    = threadIdx.x & 63;
    int row0 = blockIdx.x * (blockDim.x >> 6) + (threadIdx.x >> 6);
    int strd = gridDim.x * (blockDim.x >> 6);
    float s = 0.f, q = 0.f;
    for (int r = row0; r < NN; r += strd) {
        float v = g_summed[r * ATOMD + c];
        s += v; q += v * v;
    }
    atomicAdd(&g_s2[c], (double)s);
    atomicAdd(&g_q2[c], (double)q);
}

__global__ void k_bn2fin(const float* __restrict__ g2, const float* __restrict__ b2) {
    int c = threadIdx.x;
    double mean = g_s2[c] / (double)NN;
    double var  = g_q2[c] / (double)NN - mean * mean;
    float sc = g2[c] * (float)(1.0 / sqrt(var + (double)EPS));
    g_bn2_scale[c] = sc;
    g_bn2_shift[c] = b2[c] - (float)mean * sc;
}

// ---------------- K6: atom_out + silu + logits ---------------------------------
__global__ void k_node2(float* __restrict__ out,
                        const float* __restrict__ attW,
                        const float* __restrict__ attB) {
    int tid  = threadIdx.x;          // 256 -> 4 nodes
    int node = blockIdx.x * 4 + (tid >> 6);
    int c    = tid & 63;
    __shared__ float sh[4][2];
    float part = 0.f;
    if (node < NN) {
        float v  = g_summed[node * ATOMD + c];
        float ao = g_bn2_scale[c] * v + g_bn2_shift[c];
        out[node * ATOMD + c] = ao;
        float h = ao * sigm(ao);
        g_hnode[node * ATOMD + c] = h;
        part = h * attW[c];
    }
#pragma unroll
    for (int off = 16; off; off >>= 1)
        part += __shfl_down_sync(0xffffffff, part, off);
    if ((tid & 31) == 0) sh[tid >> 6][(tid >> 5) & 1] = part;
    __syncthreads();
    if (tid < 4) {
        int n2 = blockIdx.x * 4 + tid;
        if (n2 < NN) g_logits[n2] = sh[tid][0] + sh[tid][1] + attB[0];
    }
}

// ---------------- K7: per-graph softmax attention pooling ----------------------
__global__ void k_graph(float* __restrict__ out,
                        const int* __restrict__ batch,
                        const float* __restrict__ outW,
                        const float* __restrict__ outB) {
    int g   = blockIdx.x;
    int tid = threadIdx.x;           // 128
    __shared__ int lo_s, hi_s;
    __shared__ float red[128];
    if (tid == 0) {
        int lo = 0, hi = NN;
        while (lo < hi) { int md = (lo + hi) >> 1; if (batch[md] < g) lo = md + 1; else hi = md; }
        lo_s = lo;
        int lo2 = lo, hi2 = NN;
        while (lo2 < hi2) { int md = (lo2 + hi2) >> 1; if (batch[md] < g + 1) lo2 = md + 1; else hi2 = md; }
        hi_s = lo2;
    }
    __syncthreads();
    int lo = lo_s, hi = hi_s;
    if (lo >= hi) { if (tid == 0) out[NN * ATOMD + g] = outB[0]; return; }

    float m = -INFINITY;
    for (int n = lo + tid; n < hi; n += 128) m = fmaxf(m, g_logits[n]);
    red[tid] = m; __syncthreads();
    for (int s = 64; s; s >>= 1) { if (tid < s) red[tid] = fmaxf(red[tid], red[tid + s]); __syncthreads(); }
    m = red[0]; __syncthreads();

    float ssum = 0.f;
    for (int n = lo + tid; n < hi; n += 128) ssum += expf(g_logits[n] - m);
    red[tid] = ssum; __syncthreads();
    for (int s = 64; s; s >>= 1) { if (tid < s) red[tid] += red[tid + s]; __syncthreads(); }
    float denom = red[0]; __syncthreads();

    int c = tid & 63, half = tid >> 6;
    float acc = 0.f;
    for (int n = lo + half; n < hi; n += 2) {
        float alpha = expf(g_logits[n] - m) / denom;
        acc += alpha * g_hnode[n * ATOMD + c];
    }
    red[tid] = acc * outW[c]; __syncthreads();
    for (int s = 64; s; s >>= 1) { if (tid < s) red[tid] += red[tid + s]; __syncthreads(); }
    if (tid == 0) out[NN * ATOMD + g] = red[0] + outB[0];
}

// ---------------- launch --------------------------------------------------------
extern "C" void kernel_launch(void* const* d_in, const int* in_sizes, int n_in,
                              void* d_out, int out_size) {
    const float *x, *eattr, *lowf, *embW, *embB, *fcW, *fcB;
    const float *bn1g, *bn1b, *bn2g, *bn2b, *attW, *attB, *outW, *outB;
    const int *eidx, *batch;

    if (in_sizes[3] == 2 * NE) {
        // setup_inputs dict order
        x     = (const float*)d_in[0];  eattr = (const float*)d_in[1];
        lowf  = (const float*)d_in[2];  eidx  = (const int*)  d_in[3];
        batch = (const int*)  d_in[4];  embW  = (const float*)d_in[5];
        embB  = (const float*)d_in[6];  fcW   = (const float*)d_in[7];
        fcB   = (const float*)d_in[8];  bn1g  = (const float*)d_in[9];
        bn1b  = (const float*)d_in[10]; bn2g  = (const float*)d_in[11];
        bn2b  = (const float*)d_in[12]; attW  = (const float*)d_in[13];
        attB  = (const float*)d_in[14]; outW  = (const float*)d_in[15];
        outB  = (const float*)d_in[16];
    } else {
        // reference-signature order
        x     = (const float*)d_in[0];  eattr = (const float*)d_in[1];
        lowf  = (const float*)d_in[2];  embW  = (const float*)d_in[3];
        embB  = (const float*)d_in[4];  fcW   = (const float*)d_in[5];
        fcB   = (const float*)d_in[6];  bn1g  = (const float*)d_in[7];
        bn1b  = (const float*)d_in[8];  bn2g  = (const float*)d_in[9];
        bn2b  = (const float*)d_in[10]; attW  = (const float*)d_in[11];
        attB  = (const float*)d_in[12]; outW  = (const float*)d_in[13];
        outB  = (const float*)d_in[14]; eidx  = (const int*)  d_in[15];
        batch = (const int*)  d_in[16];
    }

    float* out = (float*)d_out;

    k_init<<<256, 512>>>();
    k_hist<<<512, 512>>>(eidx);
    k_scan<<<1, 1024>>>();
    k_scatter<<<512, 512>>>(eidx);
    k_embed<<<(NN + NPB - 1) / NPB, 256>>>(x, lowf, embW, embB);
    {
        dim3 grid((NN + NPB - 1) / NPB, 2);
        k_proj<<<grid, 256>>>(fcW);
    }
    k_edge1<<<(NE + EPB - 1) / EPB, 128>>>(eattr, eidx, fcW, fcB);
    k_bn1fin<<<1, FCO>>>(bn1g, bn1b);
    k_edge2csr<<<(NN * 32 + 255) / 256, 256>>>();
    k_bn2stats<<<128, 256>>>();
    k_bn2fin<<<1, ATOMD>>>(bn2g, bn2b);
    k_node2<<<(NN + 3) / 4, 256>>>(out, attW, attB);
    k_graph<<<NG, 128>>>(out, batch, outW, outB);
}

// round 17
// speedup vs baseline: 1.3973x; 1.3973x over previous
#include <cuda_runtime.h>
#include <cuda_fp16.h>
#include <math.h>
#include <stdint.h>

#define NN    50000
#define NE    1000000
#define NG    256
#define ORIG  92
#define ATOMD 64
#define NBR   41
#define FCO   128
#define EPS   1e-5f

// ---------------- scratch (static device globals; no allocation) -------------
__device__ float  g_af[NN * ATOMD];          // atom_fea
__device__ float  g_A1[NN * FCO];            // atom_fea @ fc_W[0:64]
__device__ float  g_A2[NN * FCO];            // atom_fea @ fc_W[64:128]
__device__ __half g_h[(size_t)NE * FCO];     // pre-BN edge hidden (256 MB, fp16)
__device__ float  g_summed[NN * ATOMD];      // segment_sum(msg, src)
__device__ float  g_hnode[NN * ATOMD];       // silu(atom_out)
__device__ float  g_logits[NN];
__device__ double g_s1[FCO], g_q1[FCO];      // bn1 sum / sumsq (fp32 h, pre-round)
__device__ double g_s2[ATOMD], g_q2[ATOMD];  // bn2 sum / sumsq
__device__ float  g_bn1_scale[FCO], g_bn1_shift[FCO];
__device__ float  g_bn2_scale[ATOMD], g_bn2_shift[ATOMD];

// ---------------- K0: zero the per-launch accumulators -----------------------
__global__ void k_init() {
    int stride = gridDim.x * blockDim.x;
    for (int i = blockIdx.x * blockDim.x + threadIdx.x; i < NN * ATOMD; i += stride)
        g_summed[i] = 0.f;
    int t = blockIdx.x * blockDim.x + threadIdx.x;
    if (t < FCO)   { g_s1[t] = 0.0; g_q1[t] = 0.0; }
    if (t < ATOMD) { g_s2[t] = 0.0; g_q2[t] = 0.0; }
}

// ---------------- K1a: atom_fea = x @ emb_W + emb_b + lower_f ----------------
#define NPB 16
__global__ void k_embed(const float* __restrict__ x,
                        const float* __restrict__ lower_f,
                        const float* __restrict__ embW,
                        const float* __restrict__ embB) {
    __shared__ __align__(16) float embW_s[ORIG * ATOMD];   // 23552 B
    __shared__ __align__(16) float x_s[NPB * ORIG];        // 5888 B
    int tid = threadIdx.x;  // 256
    int n0  = blockIdx.x * NPB;
    for (int i = tid; i < ORIG * ATOMD; i += 256) embW_s[i] = embW[i];
    for (int i = tid; i < NPB * ORIG; i += 256) {
        int node = n0 + i / ORIG;
        x_s[i] = (node < NN) ? x[node * ORIG + (i % ORIG)] : 0.f;
    }
    __syncthreads();
    for (int t = tid; t < NPB * ATOMD; t += 256) {
        int i = t >> 6, c = t & 63, node = n0 + i;
        if (node >= NN) continue;
        float acc = 0.f;
        const float4* x4 = (const float4*)(x_s + i * ORIG);
#pragma unroll
        for (int k4 = 0; k4 < ORIG / 4; k4++) {
            float4 xv = x4[k4];
            int k = k4 * 4;
            acc += xv.x * embW_s[(k + 0) * ATOMD + c];
            acc += xv.y * embW_s[(k + 1) * ATOMD + c];
            acc += xv.z * embW_s[(k + 2) * ATOMD + c];
            acc += xv.w * embW_s[(k + 3) * ATOMD + c];
        }
        g_af[node * ATOMD + c] = acc + embB[c] + lower_f[node * ATOMD + c];
    }
}

// ---------------- K1b: A1/A2 = atom_fea @ Wa/Wb (register-tiled) -------------
__global__ void k_proj(const float* __restrict__ fcW) {
    __shared__ __align__(16) float W_s[ATOMD * FCO];   // 32 KB
    __shared__ __align__(16) float at_s[NPB * ATOMD];  // 4 KB
    int tid   = threadIdx.x;        // 256
    int which = blockIdx.y;         // 0 -> A1 (rows 0..63), 1 -> A2 (rows 64..127)
    int n0    = blockIdx.x * NPB;
    const float* Wsrc = fcW + which * ATOMD * FCO;
    for (int i = tid; i < ATOMD * FCO; i += 256) W_s[i] = Wsrc[i];
    for (int i = tid; i < NPB * ATOMD; i += 256) {
        int node = n0 + (i >> 6);
        at_s[i] = (node < NN) ? g_af[node * ATOMD + (i & 63)] : 0.f;
    }
    __syncthreads();
    int j = tid & 127, ig = tid >> 7;   // 2 node-groups of 8
    float acc[8];
#pragma unroll
    for (int r = 0; r < 8; r++) acc[r] = 0.f;
    for (int c = 0; c < ATOMD; c++) {
        float w = W_s[c * FCO + j];
#pragma unroll
        for (int r = 0; r < 8; r++)
            acc[r] += at_s[(ig + 2 * r) * ATOMD + c] * w;
    }
    float* dst = which ? g_A2 : g_A1;
#pragma unroll
    for (int r = 0; r < 8; r++) {
        int node = n0 + ig + 2 * r;
        if (node < NN) dst[node * FCO + j] = acc[r];
    }
}

// ---------------- K2: edge pass 1 — h = A1[src]+A2[dst]+attr@W3+b, stats -----
// Exact R14-winning body (cp.async ring ECH=8/DEPTH=4, 2 f32x2 chains,
// 4-edge gather sub-batches). Only change: h stored as fp16.
#define EPB 512
#define ECH 8
#define DEPTH 4
__global__ void __launch_bounds__(128) k_edge1(
                        const float* __restrict__ eattr,
                        const int* __restrict__ eidx,
                        const float* __restrict__ fcW,
                        const float* __restrict__ fcB) {
    __shared__ __align__(16) float attr_s[DEPTH][ECH][44];  // 5632 B, col41 zeroed
    __shared__ int idx_s[DEPTH][2][ECH];                    // src,dst per buffer
    int tid = threadIdx.x;  // 128 -> output column c

    // packed weight k-pairs: w2[j] = (W[2j,c], W[2j+1,c]); pair 20 = (W[40,c], 0)
    unsigned long long w2[21];
#pragma unroll
    for (int j = 0; j < 20; j++) {
        float wa = fcW[(FCO + 2 * j) * FCO + tid];
        float wb = fcW[(FCO + 2 * j + 1) * FCO + tid];
        asm("mov.b64 %0, {%1,%2};" : "=l"(w2[j]) : "f"(wa), "f"(wb));
    }
    {
        float wa = fcW[(FCO + 40) * FCO + tid];
        asm("mov.b64 %0, {%1,%2};" : "=l"(w2[20]) : "f"(wa), "f"(0.0f));
    }
    float b = fcB[tid];
    float s0 = 0.f, s1 = 0.f, q0 = 0.f, q1 = 0.f;

    // zero padding column 41 in all DEPTH*ECH rows (read as hi lane of pair 20)
    if (tid < DEPTH * ECH) attr_s[tid >> 3][tid & 7][41] = 0.f;

    int e0 = blockIdx.x * EPB;

    // async-stage chunk [ce0, ce0+8) into ring buffer; ALWAYS commits a group
    auto stage = [&](int ce0) {
        if (ce0 < NE) {
            int buf = (ce0 >> 3) & (DEPTH - 1);
            const float* gbase = eattr + (size_t)ce0 * NBR;
            for (int t = tid; t < ECH * NBR; t += 128) {
                int i = t / NBR, k = t - i * NBR;
                uint32_t sa = (uint32_t)__cvta_generic_to_shared(&attr_s[buf][i][k]);
                asm volatile("cp.async.ca.shared.global [%0], [%1], 4;"
                             :: "r"(sa), "l"(gbase + t));
            }
            if (tid < ECH) {
                uint32_t sa = (uint32_t)__cvta_generic_to_shared(&idx_s[buf][0][tid]);
                asm volatile("cp.async.ca.shared.global [%0], [%1], 4;"
                             :: "r"(sa), "l"(eidx + ce0 + tid));
            } else if (tid < 2 * ECH) {
                uint32_t sa = (uint32_t)__cvta_generic_to_shared(&idx_s[buf][1][tid - ECH]);
                asm volatile("cp.async.ca.shared.global [%0], [%1], 4;"
                             :: "r"(sa), "l"(eidx + NE + ce0 + tid - ECH));
            }
        }
        asm volatile("cp.async.commit_group;" ::: "memory");
    };

    // prologue: stage chunks 0..2 (3 committed groups)
    stage(e0);
    stage(e0 + ECH);
    stage(e0 + 2 * ECH);

    const int nch = EPB / ECH;   // 64
    for (int ch = 0; ch < nch; ch++) {
        stage(e0 + (ch + 3) * ECH);
        asm volatile("cp.async.wait_group 3;" ::: "memory");  // chunk ch arrived
        __syncthreads();

        int cb = e0 + ch * ECH;
        if (cb < NE) {                      // chunks full-or-empty (NE%8==0)
            int buf = ch & (DEPTH - 1);
#pragma unroll
            for (int g = 0; g < 2; g++) {
                float base[4];
#pragma unroll
                for (int u = 0; u < 4; u++) {
                    int i = g * 4 + u;
                    base[u] = b + g_A1[idx_s[buf][0][i] * FCO + tid]
                                + g_A2[idx_s[buf][1][i] * FCO + tid];
                }
#pragma unroll
                for (int u = 0; u < 4; u++) {
                    int i = g * 4 + u;
                    unsigned long long acc0, acc1;
                    asm("mov.b64 %0, {%1,%2};" : "=l"(acc0) : "f"(base[u]), "f"(0.0f));
                    asm("mov.b64 %0, {%1,%1};" : "=l"(acc1) : "f"(0.0f));
                    const ulonglong2* a16 = (const ulonglong2*)attr_s[buf][i];
#pragma unroll
                    for (int j = 0; j < 10; j++) {
                        ulonglong2 uu = a16[j];
                        asm("fma.rn.f32x2 %0, %1, %2, %0;" : "+l"(acc0) : "l"(uu.x), "l"(w2[2 * j]));
                        asm("fma.rn.f32x2 %0, %1, %2, %0;" : "+l"(acc1) : "l"(uu.y), "l"(w2[2 * j + 1]));
                    }
                    {
                        unsigned long long u20 = ((const unsigned long long*)attr_s[buf][i])[20];
                        asm("fma.rn.f32x2 %0, %1, %2, %0;" : "+l"(acc0) : "l"(u20), "l"(w2[20]));
                    }
                    asm("add.rn.f32x2 %0, %0, %1;" : "+l"(acc0) : "l"(acc1));
                    float lo, hi;
                    asm("mov.b64 {%0,%1}, %2;" : "=f"(lo), "=f"(hi) : "l"(acc0));
                    float h = lo + hi;
                    g_h[(size_t)(cb + i) * FCO + tid] = __float2half(h);
                    if (u & 1) { s1 += h; q1 = fmaf(h, h, q1); }
                    else       { s0 += h; q0 = fmaf(h, h, q0); }
                }
            }
        }
        __syncthreads();
    }
    atomicAdd(&g_s1[tid], (double)(s0 + s1));
    atomicAdd(&g_q1[tid], (double)(q0 + q1));
}

// ---------------- K3: finalize bn1 scale/shift --------------------------------
__global__ void k_bn1fin(const float* __restrict__ g1, const float* __restrict__ b1) {
    int c = threadIdx.x;
    double mean = g_s1[c] / (double)NE;
    double var  = g_q1[c] / (double)NE - mean * mean;
    float sc = g1[c] * (float)(1.0 / sqrt(var + (double)EPS));
    g_bn1_scale[c] = sc;
    g_bn1_shift[c] = b1[c] - (float)mean * sc;
}

__device__ __forceinline__ float sigm(float x)  { return __fdividef(1.f, 1.f + __expf(-x)); }
__device__ __forceinline__ float softp(float x) { return fmaxf(x, 0.f) + __logf(1.f + __expf(-fabsf(x))); }

// ---------------- K4: edge pass 2 — msg + scatter into summed ----------------
// 16 threads per edge, 4 columns each; h read as fp16 (8B per half-row chunk).
__global__ void k_edge2(const int* __restrict__ eidx) {
    int gtid = blockIdx.x * blockDim.x + threadIdx.x;
    int e = gtid >> 4;          // 16 threads per edge
    int q = gtid & 15;          // 4 columns per thread
    if (e >= NE) return;
    const __half* hp = g_h + (size_t)e * FCO;
    int c0 = q * 4;
    uint2 uf = __ldcs((const uint2*)(hp + c0));        // 4 halves: filter cols
    uint2 ug = __ldcs((const uint2*)(hp + 64 + c0));   // 4 halves: core cols
    float2 f01 = __half22float2(*(const __half2*)&uf.x);
    float2 f23 = __half22float2(*(const __half2*)&uf.y);
    float2 g01 = __half22float2(*(const __half2*)&ug.x);
    float2 g23 = __half22float2(*(const __half2*)&ug.y);
    float4 m;
    {
        float f0 = g_bn1_scale[c0 + 0] * f01.x + g_bn1_shift[c0 + 0];
        float f1 = g_bn1_scale[c0 + 1] * f01.y + g_bn1_shift[c0 + 1];
        float f2 = g_bn1_scale[c0 + 2] * f23.x + g_bn1_shift[c0 + 2];
        float f3 = g_bn1_scale[c0 + 3] * f23.y + g_bn1_shift[c0 + 3];
        float g0 = g_bn1_scale[64 + c0 + 0] * g01.x + g_bn1_shift[64 + c0 + 0];
        float g1 = g_bn1_scale[64 + c0 + 1] * g01.y + g_bn1_shift[64 + c0 + 1];
        float g2 = g_bn1_scale[64 + c0 + 2] * g23.x + g_bn1_shift[64 + c0 + 2];
        float g3 = g_bn1_scale[64 + c0 + 3] * g23.y + g_bn1_shift[64 + c0 + 3];
        m.x = sigm(f0) * softp(g0);
        m.y = sigm(f1) * softp(g1);
        m.z = sigm(f2) * softp(g2);
        m.w = sigm(f3) * softp(g3);
    }
    int src = eidx[e];
    float* dst = g_summed + src * ATOMD + c0;
    asm volatile("red.global.add.v4.f32 [%0], {%1,%2,%3,%4};"
                 :: "l"(dst), "f"(m.x), "f"(m.y), "f"(m.z), "f"(m.w) : "memory");
}

// ---------------- K5: bn2 stats over summed -----------------------------------
__global__ void k_bn2stats() {
    int c    = threadIdx.x & 63;
    int row0 = blockIdx.x * (blockDim.x >> 6) + (threadIdx.x >> 6);
    int strd = gridDim.x * (blockDim.x >> 6);
    float s = 0.f, q = 0.f;
    for (int r = row0; r < NN; r += strd) {
        float v = g_summed[r * ATOMD + c];
        s += v; q += v * v;
    }
    atomicAdd(&g_s2[c], (double)s);
    atomicAdd(&g_q2[c], (double)q);
}

__global__ void k_bn2fin(const float* __restrict__ g2, const float* __restrict__ b2) {
    int c = threadIdx.x;
    double mean = g_s2[c] / (double)NN;
    double var  = g_q2[c] / (double)NN - mean * mean;
    float sc = g2[c] * (float)(1.0 / sqrt(var + (double)EPS));
    g_bn2_scale[c] = sc;
    g_bn2_shift[c] = b2[c] - (float)mean * sc;
}

// ---------------- K6: atom_out + silu + logits ---------------------------------
__global__ void k_node2(float* __restrict__ out,
                        const float* __restrict__ attW,
                        const float* __restrict__ attB) {
    int tid  = threadIdx.x;          // 256 -> 4 nodes
    int node = blockIdx.x * 4 + (tid >> 6);
    int c    = tid & 63;
    __shared__ float sh[4][2];
    float part = 0.f;
    if (node < NN) {
        float v  = g_summed[node * ATOMD + c];
        float ao = g_bn2_scale[c] * v + g_bn2_shift[c];
        out[node * ATOMD + c] = ao;
        float h = ao * sigm(ao);
        g_hnode[node * ATOMD + c] = h;
        part = h * attW[c];
    }
#pragma unroll
    for (int off = 16; off; off >>= 1)
        part += __shfl_down_sync(0xffffffff, part, off);
    if ((tid & 31) == 0) sh[tid >> 6][(tid >> 5) & 1] = part;
    __syncthreads();
    if (tid < 4) {
        int n2 = blockIdx.x * 4 + tid;
        if (n2 < NN) g_logits[n2] = sh[tid][0] + sh[tid][1] + attB[0];
    }
}

// ---------------- K7: per-graph softmax attention pooling ----------------------
__global__ void k_graph(float* __restrict__ out,
                        const int* __restrict__ batch,
                        const float* __restrict__ outW,
                        const float* __restrict__ outB) {
    int g   = blockIdx.x;
    int tid = threadIdx.x;           // 128
    __shared__ int lo_s, hi_s;
    __shared__ float red[128];
    if (tid == 0) {
        int lo = 0, hi = NN;
        while (lo < hi) { int md = (lo + hi) >> 1; if (batch[md] < g) lo = md + 1; else hi = md; }
        lo_s = lo;
        int lo2 = lo, hi2 = NN;
        while (lo2 < hi2) { int md = (lo2 + hi2) >> 1; if (batch[md] < g + 1) lo2 = md + 1; else hi2 = md; }
        hi_s = lo2;
    }
    __syncthreads();
    int lo = lo_s, hi = hi_s;
    if (lo >= hi) { if (tid == 0) out[NN * ATOMD + g] = outB[0]; return; }

    float m = -INFINITY;
    for (int n = lo + tid; n < hi; n += 128) m = fmaxf(m, g_logits[n]);
    red[tid] = m; __syncthreads();
    for (int s = 64; s; s >>= 1) { if (tid < s) red[tid] = fmaxf(red[tid], red[tid + s]); __syncthreads(); }
    m = red[0]; __syncthreads();

    float ssum = 0.f;
    for (int n = lo + tid; n < hi; n += 128) ssum += expf(g_logits[n] - m);
    red[tid] = ssum; __syncthreads();
    for (int s = 64; s; s >>= 1) { if (tid < s) red[tid] += red[tid + s]; __syncthreads(); }
    float denom = red[0]; __syncthreads();

    int c = tid & 63, half = tid >> 6;
    float acc = 0.f;
    for (int n = lo + half; n < hi; n += 2) {
        float alpha = expf(g_logits[n] - m) / denom;
        acc += alpha * g_hnode[n * ATOMD + c];
    }
    red[tid] = acc * outW[c]; __syncthreads();
    for (int s = 64; s; s >>= 1) { if (tid < s) red[tid] += red[tid + s]; __syncthreads(); }
    if (tid == 0) out[NN * ATOMD + g] = red[0] + outB[0];
}

// ---------------- launch --------------------------------------------------------
extern "C" void kernel_launch(void* const* d_in, const int* in_sizes, int n_in,
                              void* d_out, int out_size) {
    const float *x, *eattr, *lowf, *embW, *embB, *fcW, *fcB;
    const float *bn1g, *bn1b, *bn2g, *bn2b, *attW, *attB, *outW, *outB;
    const int *eidx, *batch;

    if (in_sizes[3] == 2 * NE) {
        // setup_inputs dict order
        x     = (const float*)d_in[0];  eattr = (const float*)d_in[1];
        lowf  = (const float*)d_in[2];  eidx  = (const int*)  d_in[3];
        batch = (const int*)  d_in[4];  embW  = (const float*)d_in[5];
        embB  = (const float*)d_in[6];  fcW   = (const float*)d_in[7];
        fcB   = (const float*)d_in[8];  bn1g  = (const float*)d_in[9];
        bn1b  = (const float*)d_in[10]; bn2g  = (const float*)d_in[11];
        bn2b  = (const float*)d_in[12]; attW  = (const float*)d_in[13];
        attB  = (const float*)d_in[14]; outW  = (const float*)d_in[15];
        outB  = (const float*)d_in[16];
    } else {
        // reference-signature order
        x     = (const float*)d_in[0];  eattr = (const float*)d_in[1];
        lowf  = (const float*)d_in[2];  embW  = (const float*)d_in[3];
        embB  = (const float*)d_in[4];  fcW   = (const float*)d_in[5];
        fcB   = (const float*)d_in[6];  bn1g  = (const float*)d_in[7];
        bn1b  = (const float*)d_in[8];  bn2g  = (const float*)d_in[9];
        bn2b  = (const float*)d_in[10]; attW  = (const float*)d_in[11];
        attB  = (const float*)d_in[12]; outW  = (const float*)d_in[13];
        outB  = (const float*)d_in[14]; eidx  = (const int*)  d_in[15];
        batch = (const int*)  d_in[16];
    }

    float* out = (float*)d_out;

    k_init<<<2048, 512>>>();
    k_embed<<<(NN + NPB - 1) / NPB, 256>>>(x, lowf, embW, embB);
    {
        dim3 grid((NN + NPB - 1) / NPB, 2);
        k_proj<<<grid, 256>>>(fcW);
    }
    k_edge1<<<(NE + EPB - 1) / EPB, 128>>>(eattr, eidx, fcW, fcB);
    k_bn1fin<<<1, FCO>>>(bn1g, bn1b);
    k_edge2<<<(NE * 16 + 255) / 256, 256>>>(eidx);
    k_bn2stats<<<128, 256>>>();
    k_bn2fin<<<1, ATOMD>>>(bn2g, bn2b);
    k_node2<<<(NN + 3) / 4, 256>>>(out, attW, attB);
    k_graph<<<NG, 128>>>(out, batch, outW, outB);
}